// round 3
// baseline (speedup 1.0000x reference)
#include <cuda_runtime.h>

#define NODES 100000
#define NEDGE 1600000

// Scratch (allocation-free rule: __device__ globals)
__device__ unsigned g_deg [NODES];
__device__ float    g_dinv[NODES];
__device__ float4   g_xs  [NODES];   // dinv-scaled input features (layer-1 messages)
__device__ float4   g_acc1[NODES];   // layer-1 aggregation accumulator
__device__ float4   g_gs  [NODES];   // dinv-scaled layer-2 messages (after fused MLP)
__device__ float4   g_acc2[NODES];   // layer-2 aggregation accumulator

__device__ __forceinline__ void red_add_v4(float4* addr, float4 v) {
    asm volatile("red.global.add.v4.f32 [%0], {%1,%2,%3,%4};"
                 :: "l"(addr), "f"(v.x), "f"(v.y), "f"(v.z), "f"(v.w)
                 : "memory");
}

__device__ __forceinline__ void red_add_u32(unsigned* addr) {
    asm volatile("red.global.add.u32 [%0], 1;" :: "l"(addr) : "memory");
}

// deg[col[e]] += 1, 8 edges/thread (two int4 loads)
__global__ void __launch_bounds__(128) k_deg_count(const int* __restrict__ col, int e) {
    int t = blockIdx.x * blockDim.x + threadIdx.x;
    int base = t * 8;
    if (base + 7 < e) {
        int4 c0 = ((const int4*)col)[t * 2];
        int4 c1 = ((const int4*)col)[t * 2 + 1];
        red_add_u32(&g_deg[c0.x]); red_add_u32(&g_deg[c0.y]);
        red_add_u32(&g_deg[c0.z]); red_add_u32(&g_deg[c0.w]);
        red_add_u32(&g_deg[c1.x]); red_add_u32(&g_deg[c1.y]);
        red_add_u32(&g_deg[c1.z]); red_add_u32(&g_deg[c1.w]);
    } else if (base < e) {
        for (int k = base; k < e; k++) red_add_u32(&g_deg[col[k]]);
    }
}

// dinv = rsqrt(deg + 1 self-loop); xs = x * dinv; acc1 init = xs (self loop)
__global__ void k_node_pre(const float4* __restrict__ x, int n) {
    int i = blockIdx.x * blockDim.x + threadIdx.x;
    if (i < n) {
        float d = rsqrtf((float)(g_deg[i] + 1u));
        g_dinv[i] = d;
        float4 v = x[i];
        v.x *= d; v.y *= d; v.z *= d; v.w *= d;
        g_xs[i]   = v;
        g_acc1[i] = v;
    }
}

// 8-wide edge scatter: dst[col[e]] += src[row[e]]
// All gathers issued before all reductions to maximize outstanding L2 ops.
__global__ void __launch_bounds__(128) k_scatter(const int* __restrict__ row,
                                                 const int* __restrict__ col,
                                                 const float4* __restrict__ src,
                                                 float4* __restrict__ dst, int e) {
    int t = blockIdx.x * blockDim.x + threadIdx.x;
    int base = t * 8;
    if (base + 7 < e) {
        int4 r0 = ((const int4*)row)[t * 2];
        int4 r1 = ((const int4*)row)[t * 2 + 1];
        int4 c0 = ((const int4*)col)[t * 2];
        int4 c1 = ((const int4*)col)[t * 2 + 1];
        float4 v0 = src[r0.x];
        float4 v1 = src[r0.y];
        float4 v2 = src[r0.z];
        float4 v3 = src[r0.w];
        float4 v4 = src[r1.x];
        float4 v5 = src[r1.y];
        float4 v6 = src[r1.z];
        float4 v7 = src[r1.w];
        red_add_v4(&dst[c0.x], v0);
        red_add_v4(&dst[c0.y], v1);
        red_add_v4(&dst[c0.z], v2);
        red_add_v4(&dst[c0.w], v3);
        red_add_v4(&dst[c1.x], v4);
        red_add_v4(&dst[c1.y], v5);
        red_add_v4(&dst[c1.z], v6);
        red_add_v4(&dst[c1.w], v7);
    } else if (base < e) {
        for (int k = base; k < e; k++) red_add_v4(&dst[col[k]], src[row[k]]);
    }
}

// Fused per-node MLP: a1 = dinv*acc1; h = relu(a1@W1 + b1); g = h@W2;
// gs = g*dinv; acc2 init = gs (self loop)
__global__ void k_mlp(const float* __restrict__ W1, const float* __restrict__ b1,
                      const float* __restrict__ W2, int n) {
    __shared__ float sW1[256];  // [4][64] row-major
    __shared__ float sB1[64];
    __shared__ float sW2[256];  // [64][4] row-major
    int tid = threadIdx.x;
    if (tid < 256) { sW1[tid] = W1[tid]; sW2[tid] = W2[tid]; }
    if (tid < 64)  { sB1[tid] = b1[tid]; }
    __syncthreads();

    int i = blockIdx.x * blockDim.x + tid;
    if (i < n) {
        float d = g_dinv[i];
        float4 a = g_acc1[i];
        a.x *= d; a.y *= d; a.z *= d; a.w *= d;
        float g0 = 0.f, g1 = 0.f, g2 = 0.f, g3 = 0.f;
        #pragma unroll
        for (int j = 0; j < 64; j++) {
            float h = sB1[j];
            h = fmaf(a.x, sW1[j],       h);
            h = fmaf(a.y, sW1[64 + j],  h);
            h = fmaf(a.z, sW1[128 + j], h);
            h = fmaf(a.w, sW1[192 + j], h);
            h = fmaxf(h, 0.0f);
            g0 = fmaf(h, sW2[j * 4 + 0], g0);
            g1 = fmaf(h, sW2[j * 4 + 1], g1);
            g2 = fmaf(h, sW2[j * 4 + 2], g2);
            g3 = fmaf(h, sW2[j * 4 + 3], g3);
        }
        float4 gs = make_float4(g0 * d, g1 * d, g2 * d, g3 * d);
        g_gs[i]   = gs;
        g_acc2[i] = gs;
    }
}

// out = dinv * acc2 + b2
__global__ void k_final(const float* __restrict__ b2, float4* __restrict__ out, int n) {
    int i = blockIdx.x * blockDim.x + threadIdx.x;
    if (i < n) {
        float d = g_dinv[i];
        float4 a = g_acc2[i];
        float4 o;
        o.x = fmaf(d, a.x, b2[0]);
        o.y = fmaf(d, a.y, b2[1]);
        o.z = fmaf(d, a.z, b2[2]);
        o.w = fmaf(d, a.w, b2[3]);
        out[i] = o;
    }
}

extern "C" void kernel_launch(void* const* d_in, const int* in_sizes, int n_in,
                              void* d_out, int out_size) {
    const float* x  = (const float*)d_in[0];
    const int*   ei = (const int*)  d_in[1];
    const float* W1 = (const float*)d_in[2];
    const float* b1 = (const float*)d_in[3];
    const float* W2 = (const float*)d_in[4];
    const float* b2 = (const float*)d_in[5];

    int n = in_sizes[0] / 4;   // N nodes (S=4)
    int e = in_sizes[1] / 2;   // E edges
    const int* row = ei;
    const int* col = ei + e;

    void *p_deg, *p_xs, *p_acc1, *p_gs, *p_acc2;
    cudaGetSymbolAddress(&p_deg,  g_deg);
    cudaGetSymbolAddress(&p_xs,   g_xs);
    cudaGetSymbolAddress(&p_acc1, g_acc1);
    cudaGetSymbolAddress(&p_gs,   g_gs);
    cudaGetSymbolAddress(&p_acc2, g_acc2);

    const int TBN = 256;          // node kernels
    const int TBE = 128;          // edge kernels
    int nb_n = (n + TBN - 1) / TBN;
    int nt_e = (e + 7) / 8;                 // edge threads (8 edges each)
    int nb_e = (nt_e + TBE - 1) / TBE;

    cudaMemsetAsync(p_deg, 0, n * sizeof(unsigned));
    k_deg_count<<<nb_e, TBE>>>(col, e);
    k_node_pre <<<nb_n, TBN>>>((const float4*)x, n);
    k_scatter  <<<nb_e, TBE>>>(row, col, (const float4*)p_xs, (float4*)p_acc1, e);
    k_mlp      <<<nb_n, TBN>>>(W1, b1, W2, n);
    k_scatter  <<<nb_e, TBE>>>(row, col, (const float4*)p_gs, (float4*)p_acc2, e);
    k_final    <<<nb_n, TBN>>>(b2, (float4*)d_out, n);
}

// round 4
// speedup vs baseline: 1.1231x; 1.1231x over previous
#include <cuda_runtime.h>

#define NODES 100000
#define NEDGE 1600000

__device__ unsigned g_deg [NODES];
__device__ float    g_dinv[NODES];
__device__ float4   g_xs  [NODES];   // dinv-scaled input features (layer-1 messages)
__device__ float4   g_acc1[NODES];   // layer-1 aggregation accumulator
__device__ float4   g_gs  [NODES];   // dinv-scaled layer-2 messages (after fused MLP)
__device__ float4   g_acc2[NODES];   // layer-2 aggregation accumulator

__device__ __forceinline__ void red_add_v4(float4* addr, float4 v) {
    asm volatile("red.global.add.v4.f32 [%0], {%1,%2,%3,%4};"
                 :: "l"(addr), "f"(v.x), "f"(v.y), "f"(v.z), "f"(v.w)
                 : "memory");
}

__device__ __forceinline__ void red_add_u32(unsigned* addr) {
    asm volatile("red.global.add.u32 [%0], 1;" :: "l"(addr) : "memory");
}

// deg[col[e]] += 1, 2 edges/thread (int2 loads), light registers -> high occ
__global__ void __launch_bounds__(256) k_deg_count(const int* __restrict__ col, int e) {
    int t = blockIdx.x * blockDim.x + threadIdx.x;
    int base = t * 2;
    if (base + 1 < e) {
        int2 c = ((const int2*)col)[t];
        red_add_u32(&g_deg[c.x]);
        red_add_u32(&g_deg[c.y]);
    } else if (base < e) {
        red_add_u32(&g_deg[col[base]]);
    }
}

// dinv = rsqrt(deg + 1 self-loop); xs = x * dinv; acc1 init = xs (self loop)
__global__ void k_node_pre(const float4* __restrict__ x, int n) {
    int i = blockIdx.x * blockDim.x + threadIdx.x;
    if (i < n) {
        float d = rsqrtf((float)(g_deg[i] + 1u));
        g_dinv[i] = d;
        float4 v = x[i];
        v.x *= d; v.y *= d; v.z *= d; v.w *= d;
        g_xs[i]   = v;
        g_acc1[i] = v;
    }
}

// 2-edge scatter: dst[col[e]] += src[row[e]]; minimal regs -> max occupancy,
// maximizing outstanding L1tex wavefronts (the binding resource).
__global__ void __launch_bounds__(256) k_scatter(const int* __restrict__ row,
                                                 const int* __restrict__ col,
                                                 const float4* __restrict__ src,
                                                 float4* __restrict__ dst, int e) {
    int t = blockIdx.x * blockDim.x + threadIdx.x;
    int base = t * 2;
    if (base + 1 < e) {
        int2 r = ((const int2*)row)[t];
        int2 c = ((const int2*)col)[t];
        float4 v0 = src[r.x];
        float4 v1 = src[r.y];
        red_add_v4(&dst[c.x], v0);
        red_add_v4(&dst[c.y], v1);
    } else if (base < e) {
        red_add_v4(&dst[col[base]], src[row[base]]);
    }
}

// Fused per-node MLP, 2 nodes/thread, vectorized weight loads:
// sW1T: [64] x float4 (W1 transposed), sW2: [64] x float4, sB1: [64]
__global__ void __launch_bounds__(256) k_mlp(const float* __restrict__ W1,
                                             const float* __restrict__ b1,
                                             const float* __restrict__ W2, int n) {
    __shared__ float sW1T[256];  // [j][i] : sW1T[j*4+i] = W1[i*64+j]
    __shared__ float sW2 [256];  // [j][c] row-major (native layout of W2)
    __shared__ float sB1 [64];
    int tid = threadIdx.x;
    if (tid < 256) {
        sW1T[(tid & 63) * 4 + (tid >> 6)] = W1[tid];  // transpose on load
        sW2[tid] = W2[tid];
    }
    if (tid < 64) sB1[tid] = b1[tid];
    __syncthreads();

    const float4* w1t = (const float4*)sW1T;
    const float4* w2  = (const float4*)sW2;

    int i0 = (blockIdx.x * blockDim.x + tid) * 2;
    if (i0 + 1 < n) {
        float d0 = g_dinv[i0],     d1 = g_dinv[i0 + 1];
        float4 a0 = g_acc1[i0],    a1 = g_acc1[i0 + 1];
        a0.x *= d0; a0.y *= d0; a0.z *= d0; a0.w *= d0;
        a1.x *= d1; a1.y *= d1; a1.z *= d1; a1.w *= d1;
        float4 g0 = make_float4(0.f, 0.f, 0.f, 0.f);
        float4 g1 = make_float4(0.f, 0.f, 0.f, 0.f);
        #pragma unroll
        for (int j = 0; j < 64; j++) {
            float4 w = w1t[j];
            float4 u = w2[j];
            float  b = sB1[j];
            float h0 = fmaf(a0.x, w.x, fmaf(a0.y, w.y, fmaf(a0.z, w.z, fmaf(a0.w, w.w, b))));
            float h1 = fmaf(a1.x, w.x, fmaf(a1.y, w.y, fmaf(a1.z, w.z, fmaf(a1.w, w.w, b))));
            h0 = fmaxf(h0, 0.0f);
            h1 = fmaxf(h1, 0.0f);
            g0.x = fmaf(h0, u.x, g0.x); g0.y = fmaf(h0, u.y, g0.y);
            g0.z = fmaf(h0, u.z, g0.z); g0.w = fmaf(h0, u.w, g0.w);
            g1.x = fmaf(h1, u.x, g1.x); g1.y = fmaf(h1, u.y, g1.y);
            g1.z = fmaf(h1, u.z, g1.z); g1.w = fmaf(h1, u.w, g1.w);
        }
        float4 s0 = make_float4(g0.x * d0, g0.y * d0, g0.z * d0, g0.w * d0);
        float4 s1 = make_float4(g1.x * d1, g1.y * d1, g1.z * d1, g1.w * d1);
        g_gs[i0]       = s0;  g_acc2[i0]     = s0;
        g_gs[i0 + 1]   = s1;  g_acc2[i0 + 1] = s1;
    } else if (i0 < n) {
        float d = g_dinv[i0];
        float4 a = g_acc1[i0];
        a.x *= d; a.y *= d; a.z *= d; a.w *= d;
        float4 g = make_float4(0.f, 0.f, 0.f, 0.f);
        #pragma unroll
        for (int j = 0; j < 64; j++) {
            float4 w = w1t[j];
            float4 u = w2[j];
            float h = fmaf(a.x, w.x, fmaf(a.y, w.y, fmaf(a.z, w.z, fmaf(a.w, w.w, sB1[j]))));
            h = fmaxf(h, 0.0f);
            g.x = fmaf(h, u.x, g.x); g.y = fmaf(h, u.y, g.y);
            g.z = fmaf(h, u.z, g.z); g.w = fmaf(h, u.w, g.w);
        }
        float4 s = make_float4(g.x * d, g.y * d, g.z * d, g.w * d);
        g_gs[i0] = s;  g_acc2[i0] = s;
    }
}

// out = dinv * acc2 + b2
__global__ void k_final(const float* __restrict__ b2, float4* __restrict__ out, int n) {
    int i = blockIdx.x * blockDim.x + threadIdx.x;
    if (i < n) {
        float d = g_dinv[i];
        float4 a = g_acc2[i];
        float4 o;
        o.x = fmaf(d, a.x, b2[0]);
        o.y = fmaf(d, a.y, b2[1]);
        o.z = fmaf(d, a.z, b2[2]);
        o.w = fmaf(d, a.w, b2[3]);
        out[i] = o;
    }
}

extern "C" void kernel_launch(void* const* d_in, const int* in_sizes, int n_in,
                              void* d_out, int out_size) {
    const float* x  = (const float*)d_in[0];
    const int*   ei = (const int*)  d_in[1];
    const float* W1 = (const float*)d_in[2];
    const float* b1 = (const float*)d_in[3];
    const float* W2 = (const float*)d_in[4];
    const float* b2 = (const float*)d_in[5];

    int n = in_sizes[0] / 4;   // N nodes (S=4)
    int e = in_sizes[1] / 2;   // E edges
    const int* row = ei;
    const int* col = ei + e;

    void *p_deg, *p_xs, *p_acc1, *p_gs, *p_acc2;
    cudaGetSymbolAddress(&p_deg,  g_deg);
    cudaGetSymbolAddress(&p_xs,   g_xs);
    cudaGetSymbolAddress(&p_acc1, g_acc1);
    cudaGetSymbolAddress(&p_gs,   g_gs);
    cudaGetSymbolAddress(&p_acc2, g_acc2);

    const int TB = 256;
    int nb_n   = (n + TB - 1) / TB;
    int nt_e2  = (e + 1) / 2;                    // 2 edges/thread
    int nb_e2  = (nt_e2 + TB - 1) / TB;
    int nt_m   = (n + 1) / 2;                    // 2 nodes/thread (mlp)
    int nb_m   = (nt_m + TB - 1) / TB;

    cudaMemsetAsync(p_deg, 0, n * sizeof(unsigned));
    k_deg_count<<<nb_e2, TB>>>(col, e);
    k_node_pre <<<nb_n,  TB>>>((const float4*)x, n);
    k_scatter  <<<nb_e2, TB>>>(row, col, (const float4*)p_xs, (float4*)p_acc1, e);
    k_mlp      <<<nb_m,  TB>>>(W1, b1, W2, n);
    k_scatter  <<<nb_e2, TB>>>(row, col, (const float4*)p_gs, (float4*)p_acc2, e);
    k_final    <<<nb_n,  TB>>>(b2, (float4*)d_out, n);
}